// round 1
// baseline (speedup 1.0000x reference)
#include <cuda_runtime.h>
#include <cstdint>

// Problem constants (fixed by the reference setup)
#define BB        64
#define NN        2048
#define MM        256
#define CTAS_PER_B 16
#define NWARPS     8
#define ROWS_PER_CTA  (NN / CTAS_PER_B)        // 128
#define ROWS_PER_WARP (ROWS_PER_CTA / NWARPS)  // 16
#define PARTS     (CTAS_PER_B * NWARPS)        // 128 partials per batch

#define EPS_COS 1e-16f
#define EPS_NRM 1e-8f

// Static scratch (no allocations allowed). 64*128*256*4 = 8.0 MB + 64 KB.
__device__ float g_acc[BB * PARTS * MM];
__device__ float g_ds [BB * PARTS * 2];

__global__ __launch_bounds__(256, 8)
void ntm_pass1(const float* __restrict__ memory,
               const float* __restrict__ kvec,
               const float* __restrict__ g,
               const float* __restrict__ w_prev,
               const int*   __restrict__ w_lu_prev)
{
    const int b     = blockIdx.y;
    const int chunk = blockIdx.x;
    const int warp  = threadIdx.x >> 5;
    const int lane  = threadIdx.x & 31;

    // ---- preload k_e (this lane's 8 columns) and compute k_nrm (warp-wide) ----
    const float* kb = kvec + b * MM + lane * 8;
    float4 ka = *(const float4*)(kb);
    float4 kb4 = *(const float4*)(kb + 4);
    float ke[8] = { ka.x + EPS_COS, ka.y + EPS_COS, ka.z + EPS_COS, ka.w + EPS_COS,
                    kb4.x + EPS_COS, kb4.y + EPS_COS, kb4.z + EPS_COS, kb4.w + EPS_COS };
    float kq = 0.f;
    #pragma unroll
    for (int j = 0; j < 8; ++j) kq = fmaf(ke[j], ke[j], kq);
    #pragma unroll
    for (int o = 16; o; o >>= 1) kq += __shfl_xor_sync(0xffffffffu, kq, o);
    const float knrm_inv = 1.0f / fmaxf(sqrtf(kq), EPS_NRM);

    const float gb = __ldg(&g[b]);

    float accv[8] = {0.f, 0.f, 0.f, 0.f, 0.f, 0.f, 0.f, 0.f};
    float D = 0.f, S = 0.f;

    const float* memB = memory + (size_t)b * NN * MM;
    const float* wrpB = w_prev + (size_t)b * 2 * NN + NN;   // w_prev[b,1,:]
    const int*   wluB = w_lu_prev + (size_t)b * NN;

    int n = chunk * ROWS_PER_CTA + warp;
    #pragma unroll 2
    for (int i = 0; i < ROWS_PER_WARP; ++i, n += NWARPS) {
        const float* row = memB + (size_t)n * MM + lane * 8;
        float4 a0 = *(const float4*)(row);
        float4 a1 = *(const float4*)(row + 4);
        float v[8] = { a0.x, a0.y, a0.z, a0.w, a1.x, a1.y, a1.z, a1.w };

        float p = 0.f, q = 0.f;
        #pragma unroll
        for (int j = 0; j < 8; ++j) {
            float ve = v[j] + EPS_COS;
            p = fmaf(ve, ke[j], p);
            q = fmaf(ve, ve, q);
        }
        #pragma unroll
        for (int o = 16; o; o >>= 1) {
            p += __shfl_xor_sync(0xffffffffu, p, o);
            q += __shfl_xor_sync(0xffffffffu, q, o);
        }
        // |x| <= 1 by Cauchy-Schwarz -> exp(x) in [1/e, e]: no max subtraction needed.
        float mnrm = fmaxf(sqrtf(q), EPS_NRM);
        float x = p * knrm_inv / mnrm;
        float e = __expf(x);

        float wrp = __ldg(&wrpB[n]);
        float wlu = (float)__ldg(&wluB[n]);
        float ww  = gb * wrp + (1.0f - gb) * wlu;
        float cn  = 1.0f - wlu;

        D += e;
        S  = fmaf(e, ww, S);
        float ec = e * cn;
        #pragma unroll
        for (int j = 0; j < 8; ++j) accv[j] = fmaf(ec, v[j], accv[j]);
    }

    // write this warp's partial
    const int part = chunk * NWARPS + warp;
    float* dst = g_acc + ((size_t)b * PARTS + part) * MM + lane * 8;
    float4 o0 = { accv[0], accv[1], accv[2], accv[3] };
    float4 o1 = { accv[4], accv[5], accv[6], accv[7] };
    *(float4*)(dst)     = o0;
    *(float4*)(dst + 4) = o1;
    if (lane == 0) {
        g_ds[((size_t)b * PARTS + part) * 2 + 0] = D;
        g_ds[((size_t)b * PARTS + part) * 2 + 1] = S;
    }
}

__global__ __launch_bounds__(256)
void ntm_pass2(const float* __restrict__ kvec, float* __restrict__ out)
{
    const int b = blockIdx.x;
    const int t = threadIdx.x;

    float acc = 0.f, D = 0.f, S = 0.f;
    const float* accB = g_acc + (size_t)b * PARTS * MM;
    const float* dsB  = g_ds  + (size_t)b * PARTS * 2;
    #pragma unroll 4
    for (int p = 0; p < PARTS; ++p) {
        acc += accB[(size_t)p * MM + t];
        D   += dsB[p * 2 + 0];
        S   += dsB[p * 2 + 1];
    }
    out[b * MM + t] = (acc + S * __ldg(&kvec[b * MM + t])) / D;
}

extern "C" void kernel_launch(void* const* d_in, const int* in_sizes, int n_in,
                              void* d_out, int out_size)
{
    // metadata order: memory, k, g, gamma, w_prev, w_lu_prev, n
    const float* memory    = (const float*)d_in[0];
    const float* kvec      = (const float*)d_in[1];
    const float* g         = (const float*)d_in[2];
    // d_in[3] = gamma (unused: only affects dead w_u/w_lu path)
    const float* w_prev    = (const float*)d_in[4];
    const int*   w_lu_prev = (const int*)  d_in[5];
    // d_in[6] = n (unused: sort path is dead code for `read`)
    float* out = (float*)d_out;

    dim3 grid1(CTAS_PER_B, BB);
    ntm_pass1<<<grid1, 256>>>(memory, kvec, g, w_prev, w_lu_prev);
    ntm_pass2<<<BB, 256>>>(kvec, out);
}

// round 2
// speedup vs baseline: 1.5661x; 1.5661x over previous
#include <cuda_runtime.h>
#include <cstdint>

#define BB     64
#define NN     2048
#define MM     256
#define CPB    32                  // CTAs per batch
#define NWARPS 8
#define RPC    (NN / CPB)          // 64 rows per CTA
#define RPW    (RPC / NWARPS)      // 8 rows per warp

#define EPS_COS 1e-16f
#define EPS_NRM 1e-8f

// Static scratch (no allocations allowed): 64*32*256*4 = 2 MB + 16 KB + counters.
__device__ float        g_acc[BB * CPB * MM];
__device__ float        g_ds [BB * CPB * 2];
__device__ unsigned int g_count[BB];           // zero-init; reset by last CTA each run

__global__ __launch_bounds__(256)
void ntm_fused(const float* __restrict__ memory,
               const float* __restrict__ kvec,
               const float* __restrict__ gvec,
               const float* __restrict__ w_prev,
               const int*   __restrict__ w_lu_prev,
               float*       __restrict__ out)
{
    __shared__ float sAcc[NWARPS * MM];
    __shared__ float sD[NWARPS], sS[NWARPS];
    __shared__ int   sLast;

    const int b     = blockIdx.y;
    const int chunk = blockIdx.x;
    const int warp  = threadIdx.x >> 5;
    const int lane  = threadIdx.x & 31;
    const int t     = threadIdx.x;

    // ---- k_e for this lane's 8 columns; warp-wide ||k_e|| ----
    const float* kb = kvec + b * MM + lane * 8;
    float4 ka = *(const float4*)(kb);
    float4 kc = *(const float4*)(kb + 4);
    float ke[8] = { ka.x + EPS_COS, ka.y + EPS_COS, ka.z + EPS_COS, ka.w + EPS_COS,
                    kc.x + EPS_COS, kc.y + EPS_COS, kc.z + EPS_COS, kc.w + EPS_COS };
    float kq = 0.f;
    #pragma unroll
    for (int j = 0; j < 8; ++j) kq = fmaf(ke[j], ke[j], kq);
    #pragma unroll
    for (int o = 16; o; o >>= 1) kq += __shfl_xor_sync(0xffffffffu, kq, o);
    const float knrm_inv = 1.0f / fmaxf(sqrtf(kq), EPS_NRM);

    const float gb = __ldg(&gvec[b]);

    float accv[8] = {0.f,0.f,0.f,0.f,0.f,0.f,0.f,0.f};
    float D = 0.f, S = 0.f;

    const int    r0   = chunk * RPC + warp * RPW;
    const float* rowp = memory + ((size_t)b * NN + r0) * MM + lane * 8;
    const float* wrpB = w_prev + (size_t)b * 2 * NN + NN + r0;   // w_prev[b,1,r0..]
    const int*   wluB = w_lu_prev + (size_t)b * NN + r0;

    #pragma unroll
    for (int i = 0; i < RPW; i += 4) {
        // front-batch 8 x LDG.128 (4 rows) for MLP
        float4 a[4][2];
        #pragma unroll
        for (int r = 0; r < 4; ++r) {
            const float* rp = rowp + (size_t)(i + r) * MM;
            a[r][0] = __ldcs((const float4*)rp);
            a[r][1] = __ldcs((const float4*)(rp + 4));
        }

        float p[4], q[4];
        #pragma unroll
        for (int r = 0; r < 4; ++r) {
            float v[8] = { a[r][0].x, a[r][0].y, a[r][0].z, a[r][0].w,
                           a[r][1].x, a[r][1].y, a[r][1].z, a[r][1].w };
            float pp = 0.f, qq = 0.f;
            #pragma unroll
            for (int j = 0; j < 8; ++j) {
                float ve = v[j] + EPS_COS;
                pp = fmaf(ve, ke[j], pp);
                qq = fmaf(ve, ve, qq);
            }
            p[r] = pp; q[r] = qq;
        }

        // interleaved butterfly reduce: 4 independent chains hide shuffle latency
        #pragma unroll
        for (int o = 16; o; o >>= 1) {
            #pragma unroll
            for (int r = 0; r < 4; ++r) {
                p[r] += __shfl_xor_sync(0xffffffffu, p[r], o);
                q[r] += __shfl_xor_sync(0xffffffffu, q[r], o);
            }
        }

        #pragma unroll
        for (int r = 0; r < 4; ++r) {
            // |x| <= 1 by Cauchy-Schwarz -> exp in [1/e, e]; no running max needed
            float mnrm = fmaxf(sqrtf(q[r]), EPS_NRM);
            float x = p[r] * knrm_inv / mnrm;
            float e = __expf(x);

            float wrp = __ldg(&wrpB[i + r]);
            float wlu = (float)__ldg(&wluB[i + r]);
            float ww  = gb * wrp + (1.0f - gb) * wlu;
            float cn  = 1.0f - wlu;

            D += e;
            S  = fmaf(e, ww, S);
            float ec = e * cn;
            #pragma unroll
            for (int j = 0; j < 8; ++j) {
                float vj = (j < 4) ? (&a[r][0].x)[j] : (&a[r][1].x)[j - 4];
                accv[j] = fmaf(ec, vj, accv[j]);
            }
        }
    }

    // ---- CTA reduction in shared memory ----
    #pragma unroll
    for (int j = 0; j < 8; ++j) sAcc[warp * MM + lane * 8 + j] = accv[j];
    if (lane == 0) { sD[warp] = D; sS[warp] = S; }
    __syncthreads();

    float cacc = 0.f;
    #pragma unroll
    for (int w = 0; w < NWARPS; ++w) cacc += sAcc[w * MM + t];
    g_acc[((size_t)b * CPB + chunk) * MM + t] = cacc;
    if (t == 0) {
        float Dc = 0.f, Sc = 0.f;
        #pragma unroll
        for (int w = 0; w < NWARPS; ++w) { Dc += sD[w]; Sc += sS[w]; }
        g_ds[((size_t)b * CPB + chunk) * 2 + 0] = Dc;
        g_ds[((size_t)b * CPB + chunk) * 2 + 1] = Sc;
    }

    // ---- last-CTA-per-batch finalizes (no second kernel) ----
    __threadfence();                // order this thread's global writes
    __syncthreads();                // all threads' writes fenced before the signal
    if (t == 0) {
        unsigned int old = atomicAdd(&g_count[b], 1u);
        sLast = (old == CPB - 1);
        if (sLast) g_count[b] = 0;  // reset for next replay (all CTAs arrived)
    }
    __syncthreads();

    if (sLast) {
        float acc = 0.f, Dt = 0.f, St = 0.f;
        #pragma unroll 8
        for (int c = 0; c < CPB; ++c)
            acc += __ldcg(&g_acc[((size_t)b * CPB + c) * MM + t]);
        #pragma unroll 8
        for (int c = 0; c < CPB; ++c) {
            Dt += __ldcg(&g_ds[((size_t)b * CPB + c) * 2 + 0]);
            St += __ldcg(&g_ds[((size_t)b * CPB + c) * 2 + 1]);
        }
        out[b * MM + t] = (acc + St * __ldg(&kvec[b * MM + t])) / Dt;
    }
}

extern "C" void kernel_launch(void* const* d_in, const int* in_sizes, int n_in,
                              void* d_out, int out_size)
{
    // metadata order: memory, k, g, gamma, w_prev, w_lu_prev, n
    const float* memory    = (const float*)d_in[0];
    const float* kvec      = (const float*)d_in[1];
    const float* g         = (const float*)d_in[2];
    // d_in[3] = gamma (dead code for `read`)
    const float* w_prev    = (const float*)d_in[4];
    const int*   w_lu_prev = (const int*)  d_in[5];
    // d_in[6] = n (dead code for `read`)
    float* out = (float*)d_out;

    dim3 grid(CPB, BB);
    ntm_fused<<<grid, 256>>>(memory, kvec, g, w_prev, w_lu_prev, out);
}